// round 2
// baseline (speedup 1.0000x reference)
#include <cuda_runtime.h>
#include <cstdint>
#include <cstddef>

#define TRIALS 4096
#define STEPS  8192
#define NSTEPS 8189        // STEPS - ORDER
#define TPC    32          // trials per CTA
#define S      128         // steps per chunk  (8192 / 128 = 64 chunks; 64*128-3 = 8189 exactly)
#define NCHUNK 64
#define SNROW  129         // float2 slots per noise row (pad: 1032B -> 2-way LDS conflicts)
#define SOROW  260         // floats per out row (256 + 4 pad; 1040B, 16B-aligned for LDS.128)
#define BLK    128

static constexpr size_t SMEM_BYTES =
    2 * TPC * SNROW * sizeof(float2) + TPC * SOROW * sizeof(float); // 99328 B

__device__ __forceinline__ void cp8(void* dst, const void* src) {
    unsigned sa = (unsigned)__cvta_generic_to_shared(dst);
    asm volatile("cp.async.ca.shared.global [%0], [%1], 8;\n"
                 :: "r"(sa), "l"(src) : "memory");
}

// Prefetch noise chunk c into buf. Chunk c>=1 covers noise[c*S-3 .. c*S+124]
// into slots 0..127 (slot sl holds the noise for local output step sl).
// Chunk 0 covers noise[0..124] into slots 3..127 (steps 0..2 come from x_0).
// ALWAYS commits a group (possibly empty) so wait_group counts stay consistent.
__device__ __forceinline__ void prefetch(int c, float2* buf, const float2* nrm,
                                         int tb, int tid) {
    if (c < NCHUNK) {
        if (c == 0) {
            const int cnt = S - 3;  // 125
            for (int e = tid; e < TPC * cnt; e += BLK) {
                int r = e / cnt, k = e - r * cnt;
                cp8(buf + r * SNROW + 3 + k,
                    nrm + (size_t)(tb + r) * NSTEPS + k);
            }
        } else {
            int nbase = c * S - 3;
            for (int e = tid; e < TPC * S; e += BLK) {
                int r = e >> 7, k = e & (S - 1);
                cp8(buf + r * SNROW + k,
                    nrm + (size_t)(tb + r) * NSTEPS + nbase + k);
            }
        }
    }
    asm volatile("cp.async.commit_group;\n" ::: "memory");
}

__global__ __launch_bounds__(BLK, 1)
void ar_kernel(const float* __restrict__ alpha, const float* __restrict__ xmu,
               const float* __restrict__ sigma, const float* __restrict__ rhop,
               const float* __restrict__ mu,    const float* __restrict__ x0,
               const float2* __restrict__ nrm,  float* __restrict__ out) {
    extern __shared__ float smem[];
    float2* sn0 = (float2*)smem;
    float2* sn1 = sn0 + TPC * SNROW;
    float*  so  = (float*)(sn1 + TPC * SNROW);

    const int tid = threadIdx.x;
    const int tb  = blockIdx.x * TPC;

    // Kick off the first two noise chunks immediately.
    prefetch(0, sn0, nrm, tb, tid);
    prefetch(1, sn1, nrm, tb, tid);

    // Per-chain state: threads 0..63 each own (trial i, dim d).
    const int i = tid >> 1, d = tid & 1;
    float a0 = 0, a1 = 0, a2 = 0, xm = 0, c0 = 0, c1v = 0, m = 0;
    float d1 = 0, d2v = 0, d3 = 0;
    if (tid < 64) {
        a0 = alpha[0 * 2 + d];
        a1 = alpha[1 * 2 + d];
        a2 = alpha[2 * 2 + d];
        xm = xmu[d];
        float rho = rhop[0];
        if (d == 0) { c0 = sigma[0];            c1v = 0.f;                                m = mu[0]; }
        else        { c0 = rho * sigma[1];      c1v = sqrtf(1.f - rho * rho) * sigma[1];  m = mu[1]; }
        int t = tb + i;
        d3  = x0[(t * 3 + 0) * 2 + d] - xm;   // oldest lag
        d2v = x0[(t * 3 + 1) * 2 + d] - xm;
        d1  = x0[(t * 3 + 2) * 2 + d] - xm;   // newest lag
    }

    float4* out4 = (float4*)out;
    const size_t rowstride4 = (size_t)STEPS * 2 / 4;  // 4096 float4 per trial

    for (int c = 0; c < NCHUNK; ++c) {
        // Oldest in-flight group (chunk c) must be complete; <=1 pending (chunk c+1).
        asm volatile("cp.async.wait_group 1;\n" ::: "memory");
        __syncthreads();  // also orders previous iteration's `so` reads before rewrite

        float2* buf = (c & 1) ? sn1 : sn0;
        if (tid < 64) {
            const float2* nb = buf + i * SNROW;
            float*        ob = so  + i * SOROW;
            int sl = 0;
            if (c == 0) {
                // steps 0..2 are exactly x_0 (dx0 + xmu)
                ob[0 + d] = d3  + xm;
                ob[2 + d] = d2v + xm;
                ob[4 + d] = d1  + xm;
                sl = 3;
            }
            #pragma unroll 4
            for (; sl < S; ++sl) {
                float2 n  = nb[sl];
                // Cholesky noise transform (off the carried dependency chain)
                float w   = fmaf(c1v, n.y, fmaf(c0, n.x, m));
                // 3-deep carried FMA chain
                float nv  = fmaf(a2, d1, fmaf(a1, d2v, fmaf(a0, d3, w)));
                ob[sl * 2 + d] = nv + xm;
                d3 = d2v; d2v = d1; d1 = nv;
            }
        }
        __syncthreads();  // `so` complete + `buf` free for reuse

        // Prefetch chunk c+2 into the buffer just freed (commits empty group past the end)
        prefetch(c + 2, (c & 1) ? sn1 : sn0, nrm, tb, tid);

        // Coalesced writeback: each trial's 256-float chunk is contiguous (1 KB), STG.128
        for (int e = tid; e < TPC * 64; e += BLK) {
            int r = e >> 6, k = e & 63;
            float4 v = *(const float4*)(so + r * SOROW + 4 * k);
            out4[(size_t)(tb + r) * rowstride4 + (size_t)c * 64 + k] = v;
        }
    }
}

extern "C" void kernel_launch(void* const* d_in, const int* in_sizes, int n_in,
                              void* d_out, int out_size) {
    // Inputs (metadata order): alpha, xmu, sigma, rho, mu, x_0, normals
    cudaFuncSetAttribute(ar_kernel, cudaFuncAttributeMaxDynamicSharedMemorySize,
                         (int)SMEM_BYTES);
    ar_kernel<<<TRIALS / TPC, BLK, SMEM_BYTES>>>(
        (const float*)d_in[0], (const float*)d_in[1], (const float*)d_in[2],
        (const float*)d_in[3], (const float*)d_in[4], (const float*)d_in[5],
        (const float2*)d_in[6], (float*)d_out);
}

// round 3
// speedup vs baseline: 1.0061x; 1.0061x over previous
#include <cuda_runtime.h>
#include <cstddef>

#define TRIALS 4096
#define STEPS  8192
#define NSTEPS 8189      // STEPS - ORDER
#define TPC    8         // trials per CTA
#define K      32        // segments per chain (LSEG*K - 3 = 8189)
#define LSEG   256
#define BLK    256       // TPC * K threads

__global__ __launch_bounds__(BLK)
void ar_scan_kernel(const float* __restrict__ alpha, const float* __restrict__ xmu,
                    const float* __restrict__ sigma, const float* __restrict__ rhop,
                    const float* __restrict__ mu,    const float* __restrict__ x0,
                    const float2* __restrict__ nrm,  float2* __restrict__ out) {
    __shared__ float ps[BLK][2][3];   // per-unit end states (pass1) -> start states (post-scan)
    __shared__ float M253[2][3][3];   // [dim][col j][row c] = (A^253)_{c,j}
    __shared__ float M256[2][3][3];

    const int tid   = threadIdx.x;
    const int i     = tid & (TPC - 1);   // trial within CTA
    const int k     = tid >> 3;          // segment index
    const int trial = blockIdx.x * TPC + i;

    // Shared constants (broadcast loads, L1-resident)
    const float A0x = alpha[0], A0y = alpha[1];
    const float A1x = alpha[2], A1y = alpha[3];
    const float A2x = alpha[4], A2y = alpha[5];
    const float xm0 = xmu[0],   xm1 = xmu[1];
    const float rho = rhop[0];
    const float c00 = sigma[0];
    const float c10 = rho * sigma[1];
    const float c11 = sqrtf(1.0f - rho * rho) * sigma[1];
    const float m0  = mu[0],    m1 = mu[1];

    // ---- Companion matrix powers (threads 0..5: dim x basis vector) ----
    if (tid < 6) {
        const int d = tid & 1, j = tid >> 1;
        const float a0 = d ? A0y : A0x, a1 = d ? A1y : A1x, a2 = d ? A2y : A2x;
        float d1 = (j == 0) ? 1.f : 0.f;
        float d2 = (j == 1) ? 1.f : 0.f;
        float d3 = (j == 2) ? 1.f : 0.f;
        #pragma unroll 1
        for (int t = 0; t < 253; ++t) {
            float nv = fmaf(a2, d1, fmaf(a1, d2, a0 * d3));
            d3 = d2; d2 = d1; d1 = nv;
        }
        M253[d][j][0] = d1; M253[d][j][1] = d2; M253[d][j][2] = d3;
        #pragma unroll
        for (int t = 0; t < 3; ++t) {
            float nv = fmaf(a2, d1, fmaf(a1, d2, a0 * d3));
            d3 = d2; d2 = d1; d1 = nv;
        }
        M256[d][j][0] = d1; M256[d][j][1] = d2; M256[d][j][2] = d3;
    }

    // ---- Pass 1: zero-start end state per (trial, segment), both dims ----
    {
        const float2* nb = nrm + (size_t)trial * NSTEPS + (k ? LSEG * k - 3 : 0);
        const int len = k ? LSEG : LSEG - 3;
        float d1x = 0, d2x = 0, d3x = 0, d1y = 0, d2y = 0, d3y = 0;
        #pragma unroll 8
        for (int j = 0; j < len; ++j) {
            float2 n  = nb[j];
            float w0  = fmaf(c00, n.x, m0);
            float w1  = fmaf(c11, n.y, fmaf(c10, n.x, m1));
            float nx  = fmaf(A2x, d1x, fmaf(A1x, d2x, fmaf(A0x, d3x, w0)));
            float ny  = fmaf(A2y, d1y, fmaf(A1y, d2y, fmaf(A0y, d3y, w1)));
            d3x = d2x; d2x = d1x; d1x = nx;
            d3y = d2y; d2y = d1y; d1y = ny;
        }
        ps[tid][0][0] = d1x; ps[tid][0][1] = d2x; ps[tid][0][2] = d3x;
        ps[tid][1][0] = d1y; ps[tid][1][1] = d2y; ps[tid][1][2] = d3y;
    }
    __syncthreads();

    // ---- Scan: threads 0..15, one per (trial, dim); 32 sequential 3x3 matvecs ----
    if (tid < 2 * TPC) {
        const int i2 = tid >> 1, d = tid & 1;
        const int tr = blockIdx.x * TPC + i2;
        const float xm = d ? xm1 : xm0;
        float s0 = x0[(tr * 3 + 2) * 2 + d] - xm;   // dx_2 (newest lag)
        float s1 = x0[(tr * 3 + 1) * 2 + d] - xm;
        float s2 = x0[(tr * 3 + 0) * 2 + d] - xm;   // dx_0 (oldest)
        for (int kk = 0; kk < K; ++kk) {
            const int u = kk * TPC + i2;
            const float p0 = ps[u][d][0], p1 = ps[u][d][1], p2 = ps[u][d][2];
            ps[u][d][0] = s0; ps[u][d][1] = s1; ps[u][d][2] = s2;  // start state for segment kk
            const float (*Mm)[3] = (kk == 0) ? M253[d] : M256[d];
            float n0 = fmaf(Mm[0][0], s0, fmaf(Mm[1][0], s1, fmaf(Mm[2][0], s2, p0)));
            float n1 = fmaf(Mm[0][1], s0, fmaf(Mm[1][1], s1, fmaf(Mm[2][1], s2, p1)));
            float n2 = fmaf(Mm[0][2], s0, fmaf(Mm[1][2], s1, fmaf(Mm[2][2], s2, p2)));
            s0 = n0; s1 = n1; s2 = n2;
        }
    }
    __syncthreads();

    // ---- Pass 2: exact recurrence from true start states, write outputs ----
    {
        float d1x = ps[tid][0][0], d2x = ps[tid][0][1], d3x = ps[tid][0][2];
        float d1y = ps[tid][1][0], d2y = ps[tid][1][1], d3y = ps[tid][1][2];
        const float2* nb = nrm + (size_t)trial * NSTEPS + (k ? LSEG * k - 3 : 0);
        float2*       ob = out + (size_t)trial * STEPS  + (k ? LSEG * k     : 3);
        const int len = k ? LSEG : LSEG - 3;
        if (k == 0) {
            float2* o0 = out + (size_t)trial * STEPS;
            o0[0] = make_float2(d3x + xm0, d3y + xm1);
            o0[1] = make_float2(d2x + xm0, d2y + xm1);
            o0[2] = make_float2(d1x + xm0, d1y + xm1);
        }
        #pragma unroll 8
        for (int j = 0; j < len; ++j) {
            float2 n  = nb[j];
            float w0  = fmaf(c00, n.x, m0);
            float w1  = fmaf(c11, n.y, fmaf(c10, n.x, m1));
            float nx  = fmaf(A2x, d1x, fmaf(A1x, d2x, fmaf(A0x, d3x, w0)));
            float ny  = fmaf(A2y, d1y, fmaf(A1y, d2y, fmaf(A0y, d3y, w1)));
            ob[j] = make_float2(nx + xm0, ny + xm1);
            d3x = d2x; d2x = d1x; d1x = nx;
            d3y = d2y; d2y = d1y; d1y = ny;
        }
    }
}

extern "C" void kernel_launch(void* const* d_in, const int* in_sizes, int n_in,
                              void* d_out, int out_size) {
    // Inputs (metadata order): alpha, xmu, sigma, rho, mu, x_0, normals
    ar_scan_kernel<<<TRIALS / TPC, BLK>>>(
        (const float*)d_in[0], (const float*)d_in[1], (const float*)d_in[2],
        (const float*)d_in[3], (const float*)d_in[4], (const float*)d_in[5],
        (const float2*)d_in[6], (float2*)d_out);
}